// round 15
// baseline (speedup 1.0000x reference)
#include <cuda_runtime.h>
#include <cuda_bf16.h>
#include <cuda_fp8.h>
#include <cstdint>

// ===========================================================================
// Problem-fixed maxima (B=4,S=2048,K=4096,N=4096)
#define M_FIX 8192
#define N_FIX 4096
#define K_FIX 4096

__device__ __nv_bfloat16 g_A[(size_t)M_FIX * K_FIX];   // bf16 dequantized activations
__device__ __nv_bfloat16 g_B[(size_t)N_FIX * K_FIX];   // bf16 scaled weights
__device__ unsigned int  g_amax_bits;                  // zero-init; re-armed by GEMM

// ===========================================================================
// Stage 1 (merged): blocks [0,ABLKS) compute amax(bf16(x));
// blocks [ABLKS, ABLKS+WBLKS) scale weights (independent of amax).
#define ABLKS 1024
#define WBLKS 1024
__global__ void amax_prepw_kernel(const float* __restrict__ x, long long nx4,
                                  const float* __restrict__ w,
                                  const float* __restrict__ wscale, long long nw4) {
    if (blockIdx.x < ABLKS) {
        const float4* x4 = reinterpret_cast<const float4*>(x);
        float m = 0.f;
        long long stride = (long long)ABLKS * blockDim.x;
        for (long long i = blockIdx.x * (long long)blockDim.x + threadIdx.x; i < nx4; i += stride) {
            float4 v = x4[i];
            m = fmaxf(m, fabsf(__bfloat162float(__float2bfloat16(v.x))));
            m = fmaxf(m, fabsf(__bfloat162float(__float2bfloat16(v.y))));
            m = fmaxf(m, fabsf(__bfloat162float(__float2bfloat16(v.z))));
            m = fmaxf(m, fabsf(__bfloat162float(__float2bfloat16(v.w))));
        }
#pragma unroll
        for (int o = 16; o > 0; o >>= 1) m = fmaxf(m, __shfl_xor_sync(0xffffffffu, m, o));
        __shared__ float sm[32];
        int lane = threadIdx.x & 31, wrp = threadIdx.x >> 5;
        if (lane == 0) sm[wrp] = m;
        __syncthreads();
        if (wrp == 0) {
            int nw = (blockDim.x + 31) >> 5;
            m = (lane < nw) ? sm[lane] : 0.f;
#pragma unroll
            for (int o = 16; o > 0; o >>= 1) m = fmaxf(m, __shfl_xor_sync(0xffffffffu, m, o));
            if (lane == 0) atomicMax(&g_amax_bits, __float_as_uint(m));
        }
    } else {
        __nv_bfloat16 sb = __float2bfloat16(wscale[0]);
        const float4* w4 = reinterpret_cast<const float4*>(w);
        ushort4* b4 = reinterpret_cast<ushort4*>(g_B);
        long long stride = (long long)WBLKS * blockDim.x;
        for (long long i = (blockIdx.x - ABLKS) * (long long)blockDim.x + threadIdx.x;
             i < nw4; i += stride) {
            float4 v = w4[i];
            ushort4 o;
            o.x = __bfloat16_as_ushort(__hmul(__float2bfloat16(v.x), sb));
            o.y = __bfloat16_as_ushort(__hmul(__float2bfloat16(v.y), sb));
            o.z = __bfloat16_as_ushort(__hmul(__float2bfloat16(v.z), sb));
            o.w = __bfloat16_as_ushort(__hmul(__float2bfloat16(v.w), sb));
            b4[i] = o;
        }
    }
}

__device__ __forceinline__ unsigned short quant1(float v, float scale, __nv_bfloat16 sb) {
    float xf = __bfloat162float(__float2bfloat16(v));    // bf16(x)
    float q  = __fdiv_rn(xf, scale);
    q = fminf(fmaxf(q, -448.0f), 448.0f);
    __nv_fp8_e4m3 f8(q);
    float fq = (float)f8;
    return __bfloat16_as_ushort(__hmul(__float2bfloat16(fq), sb));
}

__global__ void quant_kernel(const float* __restrict__ x, long long n4) {
    float amax  = __uint_as_float(g_amax_bits);
    float scale = fmaxf(amax, 1e-12f) / 448.0f;
    __nv_bfloat16 sb = __float2bfloat16(scale);
    const float4* x4 = reinterpret_cast<const float4*>(x);
    ushort4* a4 = reinterpret_cast<ushort4*>(g_A);
    long long stride = (long long)gridDim.x * blockDim.x;
    for (long long i = blockIdx.x * (long long)blockDim.x + threadIdx.x; i < n4; i += stride) {
        float4 v = x4[i];
        ushort4 o;
        o.x = quant1(v.x, scale, sb);
        o.y = quant1(v.y, scale, sb);
        o.z = quant1(v.z, scale, sb);
        o.w = quant1(v.w, scale, sb);
        a4[i] = o;
    }
}

// ===========================================================================
// HMMA GEMM (R12 winner + split fill): 128x128 CTA, BK=64, 4 warps (2M x 2N),
// warp tile 64x64, 2 CTA/SM, 255-reg budget, 3-stage cp.async, fragment
// ping-pong. Fill for stage c+2 is issued in two halves (after ks0-prefetch
// and after ks1-prefetch) to spread LSU issue pressure; one commit per stage.
// out_f32 = float( bf16(acc) + bf16(bias) )

#define BM 128
#define BN 128
#define BK 64
#define A_BYTES (BM * 128)               // 16 KB
#define B_BYTES (BN * 128)               // 16 KB
#define STAGE_BYTES (A_BYTES + B_BYTES)  // 32 KB
#define NSTAGE 3                         // 96 KB, 2 CTA/SM
#define SW128(off) ((off) ^ (((off) >> 3) & 0x70))

#define CP_ASYNC_16(dst, src) \
    asm volatile("cp.async.cg.shared.global [%0], [%1], 16;" :: "r"(dst), "l"(src))
#define CP_COMMIT() asm volatile("cp.async.commit_group;" ::: "memory")

#define LDMATRIX_X4(r0, r1, r2, r3, addr) \
    asm volatile("ldmatrix.sync.aligned.m8n8.x4.shared.b16 {%0,%1,%2,%3}, [%4];" \
        : "=r"(r0), "=r"(r1), "=r"(r2), "=r"(r3) : "r"(addr))

#define MMA_16816(c0,c1,c2,c3, a0,a1,a2,a3, b0,b1) \
    asm volatile("mma.sync.aligned.m16n8k16.row.col.f32.bf16.bf16.f32 " \
        "{%0,%1,%2,%3}, {%4,%5,%6,%7}, {%8,%9}, {%0,%1,%2,%3};" \
        : "+f"(c0), "+f"(c1), "+f"(c2), "+f"(c3) \
        : "r"(a0), "r"(a1), "r"(a2), "r"(a3), "r"(b0), "r"(b1))

__device__ __forceinline__ uint32_t smem_u32(const void* p) {
    uint32_t a;
    asm("{ .reg .u64 t; cvta.to.shared.u64 t, %1; cvt.u32.u64 %0, t; }" : "=r"(a) : "l"(p));
    return a;
}

// Half-fills: A half (8 cp.async/thread over A tile) and B half.
__device__ __forceinline__ void fill_half_A(uint32_t sbase, int stage,
                                            const __nv_bfloat16* gA,
                                            int k0, int ld_row, int ld_unit, int K) {
    const uint32_t st = (uint32_t)stage * STAGE_BYTES;
#pragma unroll
    for (int it = 0; it < 8; it++) {
        uint32_t off = (uint32_t)(ld_row + it * 16) * 128u + (uint32_t)ld_unit * 16u;
        CP_ASYNC_16(sbase + st + SW128(off), gA + (size_t)(it * 16) * K + k0);
    }
}
__device__ __forceinline__ void fill_half_B(uint32_t sbase, int stage,
                                            const __nv_bfloat16* gB,
                                            int k0, int ld_row, int ld_unit, int K) {
    const uint32_t st = (uint32_t)stage * STAGE_BYTES;
#pragma unroll
    for (int it = 0; it < 8; it++) {
        uint32_t off = (uint32_t)(ld_row + it * 16) * 128u + (uint32_t)ld_unit * 16u;
        CP_ASYNC_16(sbase + st + A_BYTES + SW128(off), gB + (size_t)(it * 16) * K + k0);
    }
}

__device__ __forceinline__ void load_afrag(uint32_t stbase, int a_r, int a_cu, int ks,
                                           uint32_t af[4][4]) {
#pragma unroll
    for (int mt = 0; mt < 4; mt++) {
        uint32_t off = (uint32_t)(a_r + mt * 16) * 128u + (uint32_t)(ks * 2 + a_cu) * 16u;
        LDMATRIX_X4(af[mt][0], af[mt][1], af[mt][2], af[mt][3], stbase + SW128(off));
    }
}

__device__ __forceinline__ void load_bfrag(uint32_t stbase_b, int b_r, int b_cu, int ks,
                                           uint32_t bf[8][2]) {
#pragma unroll
    for (int ntp = 0; ntp < 4; ntp++) {
        uint32_t off = (uint32_t)(b_r + ntp * 16) * 128u + (uint32_t)(ks * 2 + b_cu) * 16u;
        uint32_t r0, r1, r2, r3;
        LDMATRIX_X4(r0, r1, r2, r3, stbase_b + SW128(off));
        bf[ntp * 2 + 0][0] = r0; bf[ntp * 2 + 0][1] = r1;
        bf[ntp * 2 + 1][0] = r2; bf[ntp * 2 + 1][1] = r3;
    }
}

__device__ __forceinline__ void mma_tile(float acc[4][8][4], uint32_t af[4][4],
                                         uint32_t bf[8][2]) {
#pragma unroll
    for (int mt = 0; mt < 4; mt++)
#pragma unroll
        for (int nt = 0; nt < 8; nt++)
            MMA_16816(acc[mt][nt][0], acc[mt][nt][1], acc[mt][nt][2], acc[mt][nt][3],
                      af[mt][0], af[mt][1], af[mt][2], af[mt][3],
                      bf[nt][0], bf[nt][1]);
}

__global__ __launch_bounds__(128, 2) void gemm_hmma_kernel(const float* __restrict__ bias,
                                                           float* __restrict__ out,
                                                           int M, int N, int K) {
    extern __shared__ char smem[];
    const uint32_t sbase = smem_u32(smem);

    const int tid  = threadIdx.x;
    const int wid  = tid >> 5;
    const int lane = tid & 31;
    const int wm = wid & 1;          // 0..1 -> 64-row slice
    const int wn = wid >> 1;         // 0..1 -> 64-col slice
    const int bm = blockIdx.y * BM;
    const int bn = blockIdx.x * BN;

    if (blockIdx.x == 0 && blockIdx.y == 0 && tid == 0) {
        g_amax_bits = 0u;            // re-arm for next graph replay
    }

    const int ld_row  = tid >> 3;    // 0..15
    const int ld_unit = tid & 7;     // 16B unit within 128B row
    const __nv_bfloat16* gA = g_A + (size_t)(bm + ld_row) * K + ld_unit * 8;
    const __nv_bfloat16* gB = g_B + (size_t)(bn + ld_row) * K + ld_unit * 8;

    const int a_r  = wm * 64 + (lane & 15);
    const int a_cu = lane >> 4;
    const int b_r  = wn * 64 + (lane & 7) + ((lane >> 4) << 3);
    const int b_cu = (lane >> 3) & 1;

    float acc[4][8][4];
#pragma unroll
    for (int i = 0; i < 4; i++)
#pragma unroll
        for (int j = 0; j < 8; j++)
#pragma unroll
            for (int e = 0; e < 4; e++) acc[i][j][e] = 0.f;

    const int nchunks = K / BK;      // 64

    uint32_t afb[2][4][4];
    uint32_t bfb[2][8][2];

    // Prologue: fill stages 0 and 1 (one commit group each).
    fill_half_A(sbase, 0, gA, 0, ld_row, ld_unit, K);
    fill_half_B(sbase, 0, gB, 0, ld_row, ld_unit, K);
    CP_COMMIT();
    fill_half_A(sbase, 1, gA, BK, ld_row, ld_unit, K);
    fill_half_B(sbase, 1, gB, BK, ld_row, ld_unit, K);
    CP_COMMIT();

    for (int c = 0; c < nchunks; c++) {
        if (c + 1 < nchunks) {
            asm volatile("cp.async.wait_group 1;" ::: "memory");
        } else {
            asm volatile("cp.async.wait_group 0;" ::: "memory");
        }
        __syncthreads();

        const uint32_t st  = sbase + (uint32_t)(c % NSTAGE) * STAGE_BYTES;
        const uint32_t stb = st + A_BYTES;
        const bool do_fill = (c + 2 < nchunks);
        const int  fstage  = (c + 2) % NSTAGE;
        const int  fk0     = (c + 2) * BK;

        // ks0 fragments into buffer 0
        load_afrag(st, a_r, a_cu, 0, afb[0]);
        load_bfrag(stb, b_r, b_cu, 0, bfb[0]);

        // First half of stage c+2 fill (A tile) — spread LSU pressure.
        if (do_fill) fill_half_A(sbase, fstage, gA, fk0, ld_row, ld_unit, K);

        // ks0: prefetch ks1 -> buf1, MMA buf0
        load_afrag(st, a_r, a_cu, 1, afb[1]);
        load_bfrag(stb, b_r, b_cu, 1, bfb[1]);
        mma_tile(acc, afb[0], bfb[0]);

        // Second half of fill (B tile) + single commit for the stage.
        if (do_fill) {
            fill_half_B(sbase, fstage, gB, fk0, ld_row, ld_unit, K);
            CP_COMMIT();
        }

        // ks1: prefetch ks2 -> buf0, MMA buf1
        load_afrag(st, a_r, a_cu, 2, afb[0]);
        load_bfrag(stb, b_r, b_cu, 2, bfb[0]);
        mma_tile(acc, afb[1], bfb[1]);

        // ks2: prefetch ks3 -> buf1, MMA buf0
        load_afrag(st, a_r, a_cu, 3, afb[1]);
        load_bfrag(stb, b_r, b_cu, 3, bfb[1]);
        mma_tile(acc, afb[0], bfb[0]);

        // ks3: MMA buf1
        mma_tile(acc, afb[1], bfb[1]);
    }

    // Epilogue: bf16 round + bf16 bias (exact reference semantics), widen to f32.
    const int gr = lane >> 2;        // 0..7
    const int tg = lane & 3;         // 0..3
#pragma unroll
    for (int nt = 0; nt < 8; nt++) {
        const int col = bn + wn * 64 + nt * 8 + 2 * tg;
        const __nv_bfloat16 bb0 = __float2bfloat16(bias[col]);
        const __nv_bfloat16 bb1 = __float2bfloat16(bias[col + 1]);
#pragma unroll
        for (int mt = 0; mt < 4; mt++) {
            const int row0 = bm + wm * 64 + mt * 16 + gr;
            float2 v0, v1;
            v0.x = __bfloat162float(__hadd(__float2bfloat16(acc[mt][nt][0]), bb0));
            v0.y = __bfloat162float(__hadd(__float2bfloat16(acc[mt][nt][1]), bb1));
            v1.x = __bfloat162float(__hadd(__float2bfloat16(acc[mt][nt][2]), bb0));
            v1.y = __bfloat162float(__hadd(__float2bfloat16(acc[mt][nt][3]), bb1));
            *reinterpret_cast<float2*>(&out[(size_t)row0 * N + col]) = v0;
            *reinterpret_cast<float2*>(&out[(size_t)(row0 + 8) * N + col]) = v1;
        }
    }
}

// ===========================================================================
extern "C" void kernel_launch(void* const* d_in, const int* in_sizes, int n_in,
                              void* d_out, int out_size) {
    const float* x    = (const float*)d_in[0];
    const float* w    = (const float*)d_in[1];
    const float* ws   = (const float*)d_in[2];
    const float* bias = (const float*)d_in[3];
    float* out = (float*)d_out;

    long long nx = in_sizes[0];          // M*K
    long long nw = in_sizes[1];          // N*K
    int N = in_sizes[3];
    int K = (int)(nw / N);
    int M = (int)(nx / K);

    amax_prepw_kernel<<<ABLKS + WBLKS, 256>>>(x, nx >> 2, w, ws, nw >> 2);
    quant_kernel<<<2048, 256>>>(x, nx >> 2);

    static int smem_set = 0;
    if (!smem_set) {
        cudaFuncSetAttribute(gemm_hmma_kernel,
                             cudaFuncAttributeMaxDynamicSharedMemorySize, NSTAGE * STAGE_BYTES);
        smem_set = 1;
    }
    dim3 grid(N / BN, M / BM);
    gemm_hmma_kernel<<<grid, 128, NSTAGE * STAGE_BYTES>>>(bias, out, M, N, K);
}

// round 16
// speedup vs baseline: 1.0353x; 1.0353x over previous
#include <cuda_runtime.h>
#include <cuda_bf16.h>
#include <cuda_fp8.h>
#include <cstdint>

// ===========================================================================
// Problem-fixed maxima (B=4,S=2048,K=4096,N=4096)
#define M_FIX 8192
#define N_FIX 4096
#define K_FIX 4096

__device__ __nv_bfloat16 g_A[(size_t)M_FIX * K_FIX];   // bf16 dequantized activations
__device__ __nv_bfloat16 g_B[(size_t)N_FIX * K_FIX];   // bf16 scaled weights
__device__ unsigned int  g_amax_bits;                  // zero-init; re-armed by GEMM

// ===========================================================================
// Stage 1 (merged): blocks [0,ABLKS) compute amax(bf16(x));
// blocks [ABLKS, ABLKS+WBLKS) scale weights (independent of amax).
#define ABLKS 1024
#define WBLKS 1024
__global__ void amax_prepw_kernel(const float* __restrict__ x, long long nx4,
                                  const float* __restrict__ w,
                                  const float* __restrict__ wscale, long long nw4) {
    if (blockIdx.x < ABLKS) {
        const float4* x4 = reinterpret_cast<const float4*>(x);
        float m = 0.f;
        long long stride = (long long)ABLKS * blockDim.x;
        for (long long i = blockIdx.x * (long long)blockDim.x + threadIdx.x; i < nx4; i += stride) {
            float4 v = x4[i];
            m = fmaxf(m, fabsf(__bfloat162float(__float2bfloat16(v.x))));
            m = fmaxf(m, fabsf(__bfloat162float(__float2bfloat16(v.y))));
            m = fmaxf(m, fabsf(__bfloat162float(__float2bfloat16(v.z))));
            m = fmaxf(m, fabsf(__bfloat162float(__float2bfloat16(v.w))));
        }
#pragma unroll
        for (int o = 16; o > 0; o >>= 1) m = fmaxf(m, __shfl_xor_sync(0xffffffffu, m, o));
        __shared__ float sm[32];
        int lane = threadIdx.x & 31, wrp = threadIdx.x >> 5;
        if (lane == 0) sm[wrp] = m;
        __syncthreads();
        if (wrp == 0) {
            int nw = (blockDim.x + 31) >> 5;
            m = (lane < nw) ? sm[lane] : 0.f;
#pragma unroll
            for (int o = 16; o > 0; o >>= 1) m = fmaxf(m, __shfl_xor_sync(0xffffffffu, m, o));
            if (lane == 0) atomicMax(&g_amax_bits, __float_as_uint(m));
        }
    } else {
        __nv_bfloat16 sb = __float2bfloat16(wscale[0]);
        const float4* w4 = reinterpret_cast<const float4*>(w);
        ushort4* b4 = reinterpret_cast<ushort4*>(g_B);
        long long stride = (long long)WBLKS * blockDim.x;
        for (long long i = (blockIdx.x - ABLKS) * (long long)blockDim.x + threadIdx.x;
             i < nw4; i += stride) {
            float4 v = w4[i];
            ushort4 o;
            o.x = __bfloat16_as_ushort(__hmul(__float2bfloat16(v.x), sb));
            o.y = __bfloat16_as_ushort(__hmul(__float2bfloat16(v.y), sb));
            o.z = __bfloat16_as_ushort(__hmul(__float2bfloat16(v.z), sb));
            o.w = __bfloat16_as_ushort(__hmul(__float2bfloat16(v.w), sb));
            b4[i] = o;
        }
    }
}

__device__ __forceinline__ unsigned short quant1(float v, float scale, __nv_bfloat16 sb) {
    float xf = __bfloat162float(__float2bfloat16(v));    // bf16(x)
    float q  = __fdiv_rn(xf, scale);
    q = fminf(fmaxf(q, -448.0f), 448.0f);
    __nv_fp8_e4m3 f8(q);
    float fq = (float)f8;
    return __bfloat16_as_ushort(__hmul(__float2bfloat16(fq), sb));
}

__global__ void quant_kernel(const float* __restrict__ x, long long n4) {
    float amax  = __uint_as_float(g_amax_bits);
    float scale = fmaxf(amax, 1e-12f) / 448.0f;
    __nv_bfloat16 sb = __float2bfloat16(scale);
    const float4* x4 = reinterpret_cast<const float4*>(x);
    ushort4* a4 = reinterpret_cast<ushort4*>(g_A);
    long long stride = (long long)gridDim.x * blockDim.x;
    for (long long i = blockIdx.x * (long long)blockDim.x + threadIdx.x; i < n4; i += stride) {
        float4 v = x4[i];
        ushort4 o;
        o.x = quant1(v.x, scale, sb);
        o.y = quant1(v.y, scale, sb);
        o.z = quant1(v.z, scale, sb);
        o.w = quant1(v.w, scale, sb);
        a4[i] = o;
    }
}

// ===========================================================================
// HMMA GEMM (R12 winner, final): 128x128 CTA tile, BK=64, 4 warps (2M x 2N),
// warp tile 64x64, 2 CTA/SM, 255-reg budget -> real fragment double-buffering.
// 3-stage cp.async pipeline, single burst fill per stage.
// out_f32 = float( bf16(acc) + bf16(bias) )

#define BM 128
#define BN 128
#define BK 64
#define A_BYTES (BM * 128)               // 16 KB
#define B_BYTES (BN * 128)               // 16 KB
#define STAGE_BYTES (A_BYTES + B_BYTES)  // 32 KB
#define NSTAGE 3                         // 96 KB, 2 CTA/SM
#define SW128(off) ((off) ^ (((off) >> 3) & 0x70))

#define CP_ASYNC_16(dst, src) \
    asm volatile("cp.async.cg.shared.global [%0], [%1], 16;" :: "r"(dst), "l"(src))
#define CP_COMMIT() asm volatile("cp.async.commit_group;" ::: "memory")

#define LDMATRIX_X4(r0, r1, r2, r3, addr) \
    asm volatile("ldmatrix.sync.aligned.m8n8.x4.shared.b16 {%0,%1,%2,%3}, [%4];" \
        : "=r"(r0), "=r"(r1), "=r"(r2), "=r"(r3) : "r"(addr))

#define MMA_16816(c0,c1,c2,c3, a0,a1,a2,a3, b0,b1) \
    asm volatile("mma.sync.aligned.m16n8k16.row.col.f32.bf16.bf16.f32 " \
        "{%0,%1,%2,%3}, {%4,%5,%6,%7}, {%8,%9}, {%0,%1,%2,%3};" \
        : "+f"(c0), "+f"(c1), "+f"(c2), "+f"(c3) \
        : "r"(a0), "r"(a1), "r"(a2), "r"(a3), "r"(b0), "r"(b1))

__device__ __forceinline__ uint32_t smem_u32(const void* p) {
    uint32_t a;
    asm("{ .reg .u64 t; cvta.to.shared.u64 t, %1; cvt.u32.u64 %0, t; }" : "=r"(a) : "l"(p));
    return a;
}

// 128 threads: ld_row = tid>>3 (0..15), ld_unit = tid&7; 8 iters of 16 rows each.
__device__ __forceinline__ void fill_stage(uint32_t sbase, int stage,
                                           const __nv_bfloat16* gA, const __nv_bfloat16* gB,
                                           int k0, int ld_row, int ld_unit, int K) {
    const uint32_t st = (uint32_t)stage * STAGE_BYTES;
#pragma unroll
    for (int it = 0; it < 8; it++) {
        uint32_t off = (uint32_t)(ld_row + it * 16) * 128u + (uint32_t)ld_unit * 16u;
        uint32_t sw = SW128(off);
        CP_ASYNC_16(sbase + st + sw, gA + (size_t)(it * 16) * K + k0);
        CP_ASYNC_16(sbase + st + A_BYTES + sw, gB + (size_t)(it * 16) * K + k0);
    }
    CP_COMMIT();
}

__global__ __launch_bounds__(128, 2) void gemm_hmma_kernel(const float* __restrict__ bias,
                                                           float* __restrict__ out,
                                                           int M, int N, int K) {
    extern __shared__ char smem[];
    const uint32_t sbase = smem_u32(smem);

    const int tid  = threadIdx.x;
    const int wid  = tid >> 5;
    const int lane = tid & 31;
    const int wm = wid & 1;          // 0..1 -> 64-row slice
    const int wn = wid >> 1;         // 0..1 -> 64-col slice
    const int bm = blockIdx.y * BM;
    const int bn = blockIdx.x * BN;

    // Re-arm the dynamic-quant amax accumulator for the next graph replay.
    if (blockIdx.x == 0 && blockIdx.y == 0 && tid == 0) {
        g_amax_bits = 0u;
    }

    const int ld_row  = tid >> 3;    // 0..15
    const int ld_unit = tid & 7;     // 16B unit within 128B row
    const __nv_bfloat16* gA = g_A + (size_t)(bm + ld_row) * K + ld_unit * 8;
    const __nv_bfloat16* gB = g_B + (size_t)(bn + ld_row) * K + ld_unit * 8;

    // ldmatrix addressing
    const int a_r  = wm * 64 + (lane & 15);
    const int a_cu = lane >> 4;                 // 0/1 -> k0 / k+8 halves
    const int b_r  = wn * 64 + (lane & 7) + ((lane >> 4) << 3);
    const int b_cu = (lane >> 3) & 1;

    float acc[4][8][4];
#pragma unroll
    for (int i = 0; i < 4; i++)
#pragma unroll
        for (int j = 0; j < 8; j++)
#pragma unroll
            for (int e = 0; e < 4; e++) acc[i][j][e] = 0.f;

    const int nchunks = K / BK;      // 64

    // Prologue: NSTAGE-1 = 2 stages ahead
    fill_stage(sbase, 0, gA, gB, 0, ld_row, ld_unit, K);
    fill_stage(sbase, 1, gA, gB, BK, ld_row, ld_unit, K);

    // Ping-pong fragment buffers: real registers at the 255-reg budget.
    uint32_t afb[2][4][4];
    uint32_t bfb[2][8][2];

    for (int c = 0; c < nchunks; c++) {
        if (c + 1 < nchunks) {
            asm volatile("cp.async.wait_group 1;" ::: "memory");
        } else {
            asm volatile("cp.async.wait_group 0;" ::: "memory");
        }
        __syncthreads();

        const uint32_t st = (uint32_t)(c % NSTAGE) * STAGE_BYTES;

        // Load ks=0 fragments into buffer 0
#pragma unroll
        for (int mt = 0; mt < 4; mt++) {
            uint32_t off = (uint32_t)(a_r + mt * 16) * 128u + (uint32_t)(a_cu) * 16u;
            LDMATRIX_X4(afb[0][mt][0], afb[0][mt][1], afb[0][mt][2], afb[0][mt][3],
                        sbase + st + SW128(off));
        }
#pragma unroll
        for (int ntp = 0; ntp < 4; ntp++) {
            uint32_t off = (uint32_t)(b_r + ntp * 16) * 128u + (uint32_t)(b_cu) * 16u;
            uint32_t r0, r1, r2, r3;
            LDMATRIX_X4(r0, r1, r2, r3, sbase + st + A_BYTES + SW128(off));
            bfb[0][ntp * 2 + 0][0] = r0; bfb[0][ntp * 2 + 0][1] = r1;
            bfb[0][ntp * 2 + 1][0] = r2; bfb[0][ntp * 2 + 1][1] = r3;
        }

        // Next-next stage fill overlaps the ks0 LDSM latency.
        if (c + 2 < nchunks) {
            fill_stage(sbase, (c + 2) % NSTAGE, gA, gB, (c + 2) * BK, ld_row, ld_unit, K);
        }

#pragma unroll
        for (int ks = 0; ks < 4; ks++) {
            const int cur = ks & 1;
            const int nxt = cur ^ 1;
            if (ks < 3) {
#pragma unroll
                for (int mt = 0; mt < 4; mt++) {
                    uint32_t off = (uint32_t)(a_r + mt * 16) * 128u
                                 + (uint32_t)((ks + 1) * 2 + a_cu) * 16u;
                    LDMATRIX_X4(afb[nxt][mt][0], afb[nxt][mt][1],
                                afb[nxt][mt][2], afb[nxt][mt][3],
                                sbase + st + SW128(off));
                }
#pragma unroll
                for (int ntp = 0; ntp < 4; ntp++) {
                    uint32_t off = (uint32_t)(b_r + ntp * 16) * 128u
                                 + (uint32_t)((ks + 1) * 2 + b_cu) * 16u;
                    uint32_t r0, r1, r2, r3;
                    LDMATRIX_X4(r0, r1, r2, r3, sbase + st + A_BYTES + SW128(off));
                    bfb[nxt][ntp * 2 + 0][0] = r0; bfb[nxt][ntp * 2 + 0][1] = r1;
                    bfb[nxt][ntp * 2 + 1][0] = r2; bfb[nxt][ntp * 2 + 1][1] = r3;
                }
            }
#pragma unroll
            for (int mt = 0; mt < 4; mt++)
#pragma unroll
                for (int nt = 0; nt < 8; nt++)
                    MMA_16816(acc[mt][nt][0], acc[mt][nt][1], acc[mt][nt][2], acc[mt][nt][3],
                              afb[cur][mt][0], afb[cur][mt][1],
                              afb[cur][mt][2], afb[cur][mt][3],
                              bfb[cur][nt][0], bfb[cur][nt][1]);
        }
    }

    // Epilogue: bf16 round + bf16 bias (exact reference semantics), widen to f32.
    const int gr = lane >> 2;        // 0..7
    const int tg = lane & 3;         // 0..3
#pragma unroll
    for (int nt = 0; nt < 8; nt++) {
        const int col = bn + wn * 64 + nt * 8 + 2 * tg;
        const __nv_bfloat16 bb0 = __float2bfloat16(bias[col]);
        const __nv_bfloat16 bb1 = __float2bfloat16(bias[col + 1]);
#pragma unroll
        for (int mt = 0; mt < 4; mt++) {
            const int row0 = bm + wm * 64 + mt * 16 + gr;
            float2 v0, v1;
            v0.x = __bfloat162float(__hadd(__float2bfloat16(acc[mt][nt][0]), bb0));
            v0.y = __bfloat162float(__hadd(__float2bfloat16(acc[mt][nt][1]), bb1));
            v1.x = __bfloat162float(__hadd(__float2bfloat16(acc[mt][nt][2]), bb0));
            v1.y = __bfloat162float(__hadd(__float2bfloat16(acc[mt][nt][3]), bb1));
            *reinterpret_cast<float2*>(&out[(size_t)row0 * N + col]) = v0;
            *reinterpret_cast<float2*>(&out[(size_t)(row0 + 8) * N + col]) = v1;
        }
    }
}

// ===========================================================================
extern "C" void kernel_launch(void* const* d_in, const int* in_sizes, int n_in,
                              void* d_out, int out_size) {
    const float* x    = (const float*)d_in[0];
    const float* w    = (const float*)d_in[1];
    const float* ws   = (const float*)d_in[2];
    const float* bias = (const float*)d_in[3];
    float* out = (float*)d_out;

    long long nx = in_sizes[0];          // M*K
    long long nw = in_sizes[1];          // N*K
    int N = in_sizes[3];
    int K = (int)(nw / N);
    int M = (int)(nx / K);

    amax_prepw_kernel<<<ABLKS + WBLKS, 256>>>(x, nx >> 2, w, ws, nw >> 2);
    quant_kernel<<<2048, 256>>>(x, nx >> 2);

    static int smem_set = 0;
    if (!smem_set) {
        cudaFuncSetAttribute(gemm_hmma_kernel,
                             cudaFuncAttributeMaxDynamicSharedMemorySize, NSTAGE * STAGE_BYTES);
        smem_set = 1;
    }
    dim3 grid(N / BN, M / BM);
    gemm_hmma_kernel<<<grid, 128, NSTAGE * STAGE_BYTES>>>(bias, out, M, N, K);
}